// round 16
// baseline (speedup 1.0000x reference)
#include <cuda_runtime.h>
#include <cuda_fp16.h>
#include <math.h>
#include <stdint.h>

#define Bsz 64
#define DFd 768
#define Fd  676
#define Cd  3129
#define DWd 300
#define DTd 1024
#define TK  10

// ---------------- device scratch (static, allocation-free) ----------------
__device__ int    g_topk[Bsz*TK];
__device__ float  g_emb [Bsz*TK*DWd];
__device__ float  g_cls1[Bsz*TK*DTd];
__device__ float  g_cls [Bsz*TK*DTd];
__device__ float  g_v   [(size_t)Bsz*Fd*DTd];   // 177 MB
__device__ float  g_bap [Bsz*DTd];
__device__ float  g_bap2[Bsz*DTd];
__device__ __half g_wh[DTd*DFd];                // W^T hi [n][k]
__device__ __half g_wl[DTd*DFd];                // W^T lo [n][k]

__device__ __forceinline__ void mma16816(float* c, const uint32_t* a, const uint32_t* b) {
    asm volatile(
        "mma.sync.aligned.m16n8k16.row.col.f32.f16.f16.f32 "
        "{%0,%1,%2,%3}, {%4,%5,%6,%7}, {%8,%9}, {%0,%1,%2,%3};"
        : "+f"(c[0]), "+f"(c[1]), "+f"(c[2]), "+f"(c[3])
        : "r"(a[0]), "r"(a[1]), "r"(a[2]), "r"(a[3]), "r"(b[0]), "r"(b[1]));
}
#define LDSM4(r0,r1,r2,r3,addr) \
    asm volatile("ldmatrix.sync.aligned.m8n8.x4.shared.b16 {%0,%1,%2,%3}, [%4];" \
                 : "=r"(r0), "=r"(r1), "=r"(r2), "=r"(r3) : "r"(addr))
__device__ __forceinline__ void split2(float x, __half& h, __half& l) {
    h = __float2half_rn(x);
    l = __float2half_rn(x - __half2float(h));
}
__device__ __forceinline__ uint32_t pk2(__half a, __half b) {
    __half2 t = __halves2half2(a, b);
    return *(uint32_t*)&t;
}
__device__ __forceinline__ void cp16(uint32_t dst, const void* src, int nbytes) {
    asm volatile("cp.async.cg.shared.global [%0], [%1], 16, %2;"
                 :: "r"(dst), "l"(src), "r"(nbytes));
}
__device__ __forceinline__ uint32_t smem_u32(const void* p) {
    uint32_t a;
    asm("{ .reg .u64 t; cvta.to.shared.u64 t, %1; cvt.u32.u64 %0, t; }" : "=r"(a) : "l"(p));
    return a;
}

// ============ W preconvert: W_v [k][n] -> g_wh/g_wl [n][k] =================
__global__ void convW_kernel(const float* __restrict__ Wv) {
    __shared__ float tile[32][33];
    int n0 = blockIdx.x * 32, k0 = blockIdx.y * 32;
    int tx = threadIdx.x & 31, ty = threadIdx.x >> 5;
    #pragma unroll
    for (int j = 0; j < 4; j++)
        tile[ty + j*8][tx] = Wv[(size_t)(k0 + ty + j*8) * DTd + n0 + tx];
    __syncthreads();
    #pragma unroll
    for (int j = 0; j < 4; j++) {
        int n = n0 + ty + j*8, k = k0 + tx;
        __half h, l; split2(tile[tx][ty + j*8], h, l);
        size_t o = (size_t)n * DFd + k;
        g_wh[o] = h; g_wl[o] = l;
    }
}

// ============ v-GEMM v5: A fp32-staged + in-smem convert, ldmatrix HMMA ===
#define AH_IX 0
#define AL_IX 5120          // halves
#define A_HST 40
#define B_ST  40
#define B_BASE   20480
#define B_STAGEB 20480
#define A_BASE   61440
#define A_STAGEB 16896
#define VSMEM5   95232

__global__ void __launch_bounds__(256, 2)
vgemm5_kernel(const float* __restrict__ ftm, const float* __restrict__ bias,
              float* __restrict__ outv)
{
    extern __shared__ char smraw[];
    __half* smh = (__half*)smraw;
    int tid  = threadIdx.x;
    int w    = tid >> 5, lane = tid & 31;
    int b    = blockIdx.z;
    int m0   = blockIdx.y * 128, n0 = blockIdx.x * 128;
    uint32_t smb = smem_u32(smraw);

    const float* Ab = ftm + (size_t)b * DFd * Fd;

    auto fill = [&](int s, int k0) {
        uint32_t abase = smb + A_BASE + (uint32_t)s * A_STAGEB;
        uint32_t bbase = smb + B_BASE + (uint32_t)s * B_STAGEB;
        #pragma unroll
        for (int i = 0; i < 8; i++) {
            int idx = tid + i * 256;
            if (idx < 1024) {                    // A fp32 [32k][132f]
                int k = idx >> 5, c = idx & 31;
                uint32_t dst = abase + (uint32_t)(k * 132 + c * 4) * 4;
                int nb = (m0 + c * 4 + 4 <= Fd) ? 16 : 0;
                const float* src = Ab + (size_t)(k0 + k) * Fd + (nb ? (m0 + c * 4) : 0);
                cp16(dst, src, nb);
            } else {                             // B halves [128n][40k] x2 limbs
                int j = idx - 1024;
                int limb = j >> 9, wi = j & 511;
                int n = wi >> 2, c = wi & 3;
                const __half* src = (limb ? g_wl : g_wh) + (size_t)(n0 + n) * DFd + k0 + c * 8;
                uint32_t dst = bbase + (uint32_t)(limb * 5120 + n * B_ST + c * 8) * 2;
                cp16(dst, src, 16);
            }
        }
        asm volatile("cp.async.commit_group;" ::: "memory");
    };

    fill(0, 0);

    int wm = (w & 3) * 32;
    int wn = (w >> 2) * 64;
    bool mma_active = (m0 + wm) < Fd;

    int aOff = (wm + (lane & 15)) * A_HST + (lane >> 4) * 8;
    int bOff = (wn + ((lane >> 4) & 1) * 8 + (lane & 7)) * B_ST + ((lane >> 3) & 1) * 8;
    int cf  = (w & 3) * 32 + lane;
    int cc0 = (w >> 2) * 2;

    float acc[2][8][4];
    #pragma unroll
    for (int mt = 0; mt < 2; mt++)
        #pragma unroll
        for (int nt = 0; nt < 8; nt++)
            #pragma unroll
            for (int q = 0; q < 4; q++) acc[mt][nt][q] = 0.f;

    const int NK = DFd / 32;    // 24
    for (int kb = 0; kb < NK; kb++) {
        if (kb + 1 < NK) {
            fill((kb + 1) & 1, (kb + 1) * 32);
            asm volatile("cp.async.wait_group 1;" ::: "memory");
        } else {
            asm volatile("cp.async.wait_group 0;" ::: "memory");
        }
        __syncthreads();
        {
            const float* sA = (const float*)(smraw + A_BASE + (size_t)(kb & 1) * A_STAGEB);
            #pragma unroll
            for (int ci = 0; ci < 2; ci++) {
                int c = cc0 + ci;
                float v[8];
                #pragma unroll
                for (int j = 0; j < 8; j++)
                    v[j] = sA[(c * 8 + j) * 132 + cf];
                uint32_t hh[4], ll[4];
                #pragma unroll
                for (int j = 0; j < 4; j++) {
                    __half h0, l0, h1, l1;
                    split2(v[2*j],   h0, l0);
                    split2(v[2*j+1], h1, l1);
                    hh[j] = pk2(h0, h1);
                    ll[j] = pk2(l0, l1);
                }
                *(uint4*)&smh[AH_IX + cf * A_HST + c * 8] = make_uint4(hh[0], hh[1], hh[2], hh[3]);
                *(uint4*)&smh[AL_IX + cf * A_HST + c * 8] = make_uint4(ll[0], ll[1], ll[2], ll[3]);
            }
        }
        __syncthreads();
        if (mma_active) {
            uint32_t bstage = smb + B_BASE + (uint32_t)(kb & 1) * B_STAGEB;
            #pragma unroll
            for (int ks = 0; ks < 32; ks += 16) {
                uint32_t ah[2][4], al[2][4];
                #pragma unroll
                for (int mt = 0; mt < 2; mt++) {
                    LDSM4(ah[mt][0], ah[mt][1], ah[mt][2], ah[mt][3],
                          smb + (uint32_t)(AH_IX + aOff + mt * 16 * A_HST + ks) * 2);
                    LDSM4(al[mt][0], al[mt][1], al[mt][2], al[mt][3],
                          smb + (uint32_t)(AL_IX + aOff + mt * 16 * A_HST + ks) * 2);
                }
                uint32_t bh[8][2], bl[8][2];
                #pragma unroll
                for (int p = 0; p < 4; p++) {
                    LDSM4(bh[2*p][0], bh[2*p][1], bh[2*p+1][0], bh[2*p+1][1],
                          bstage + (uint32_t)(bOff + p * 16 * B_ST + ks) * 2);
                    LDSM4(bl[2*p][0], bl[2*p][1], bl[2*p+1][0], bl[2*p+1][1],
                          bstage + (uint32_t)(5120 + bOff + p * 16 * B_ST + ks) * 2);
                }
                #pragma unroll
                for (int mt = 0; mt < 2; mt++)
                    #pragma unroll
                    for (int nt = 0; nt < 8; nt++) {
                        mma16816(acc[mt][nt], ah[mt], bh[nt]);
                        mma16816(acc[mt][nt], ah[mt], bl[nt]);
                        mma16816(acc[mt][nt], al[mt], bh[nt]);
                    }
            }
        }
        __syncthreads();
    }

    float* Cb = outv + (size_t)b * Fd * DTd;
    #pragma unroll
    for (int mt = 0; mt < 2; mt++) {
        #pragma unroll
        for (int nt = 0; nt < 8; nt++) {
            int col = n0 + wn + nt*8 + (lane & 3) * 2;
            float b0 = bias[col], b1 = bias[col+1];
            int r0 = m0 + wm + mt*16 + (lane >> 2);
            if (r0 < Fd) {
                float2 o;
                o.x = fmaxf(acc[mt][nt][0] + b0, 0.f);
                o.y = fmaxf(acc[mt][nt][1] + b1, 0.f);
                *(float2*)(Cb + (size_t)r0 * DTd + col) = o;
            }
            int r1 = r0 + 8;
            if (r1 < Fd) {
                float2 o;
                o.x = fmaxf(acc[mt][nt][2] + b0, 0.f);
                o.y = fmaxf(acc[mt][nt][3] + b1, 0.f);
                *(float2*)(Cb + (size_t)r1 * DTd + col) = o;
            }
        }
    }
}

// ================= fp16x2-split GEMM for cls ===============================
#define SM_STRIDE 34
#define AHo 0
#define ALo (128*SM_STRIDE)
#define BHo (2*128*SM_STRIDE)
#define BLo (3*128*SM_STRIDE)

__global__ void __launch_bounds__(256)
tgemm_kernel(const float* __restrict__ A, const float* __restrict__ Bm,
             const float* __restrict__ bias, float* __restrict__ Cm,
             int Md, int Kd)
{
    __shared__ __half sm[4*128*SM_STRIDE];
    int tid  = threadIdx.x;
    int w    = tid >> 5, lane = tid & 31;
    int m0   = blockIdx.y * 128, n0 = blockIdx.x * 128;
    int nk = (Kd + 31) / 32;

    float pa[16], pb[16];
    {
        int k0 = 0;
        #pragma unroll
        for (int rr = 0; rr < 16; rr++) {
            int m = m0 + w*16 + rr;
            pa[rr] = (m < Md && k0+lane < Kd) ? A[(size_t)m*Kd + k0 + lane] : 0.f;
        }
        #pragma unroll
        for (int i = 0; i < 4; i++) {
            int k = 8*i + w;
            const float* col = Bm + (size_t)(k0 + k) * DTd + n0;
            #pragma unroll
            for (int j = 0; j < 4; j++)
                pb[i*4+j] = (k0+k < Kd) ? col[lane + 32*j] : 0.f;
        }
    }
    {
        #pragma unroll
        for (int rr = 0; rr < 16; rr++) {
            __half h, l; split2(pa[rr], h, l);
            sm[AHo + (w*16+rr)*SM_STRIDE + lane] = h;
            sm[ALo + (w*16+rr)*SM_STRIDE + lane] = l;
        }
        #pragma unroll
        for (int i = 0; i < 4; i++) {
            int k = 8*i + w;
            #pragma unroll
            for (int j = 0; j < 4; j++) {
                int nl = lane + 32*j;
                __half h, l; split2(pb[i*4+j], h, l);
                sm[BHo + nl*SM_STRIDE + k] = h;
                sm[BLo + nl*SM_STRIDE + k] = l;
            }
        }
    }
    __syncthreads();

    int wm = (w & 3) * 32;
    int wn = (w >> 2) * 64;
    float acc[2][8][4];
    #pragma unroll
    for (int mt = 0; mt < 2; mt++)
        #pragma unroll
        for (int nt = 0; nt < 8; nt++)
            #pragma unroll
            for (int q = 0; q < 4; q++) acc[mt][nt][q] = 0.f;

    for (int kb = 0; kb < nk; kb++) {
        if (kb + 1 < nk) {
            int k0 = (kb + 1) * 32;
            #pragma unroll
            for (int rr = 0; rr < 16; rr++) {
                int m = m0 + w*16 + rr;
                pa[rr] = (m < Md && k0+lane < Kd) ? A[(size_t)m*Kd + k0 + lane] : 0.f;
            }
            #pragma unroll
            for (int i = 0; i < 4; i++) {
                int k = 8*i + w;
                const float* col = Bm + (size_t)(k0 + k) * DTd + n0;
                #pragma unroll
                for (int j = 0; j < 4; j++)
                    pb[i*4+j] = (k0+k < Kd) ? col[lane + 32*j] : 0.f;
            }
        }
        #pragma unroll
        for (int ks = 0; ks < 32; ks += 16) {
            uint32_t ah[2][4], al[2][4];
            #pragma unroll
            for (int mt = 0; mt < 2; mt++) {
                int base = (wm + mt*16 + (lane >> 2)) * SM_STRIDE + ks + (lane & 3) * 2;
                ah[mt][0] = *(const uint32_t*)&sm[AHo + base];
                ah[mt][1] = *(const uint32_t*)&sm[AHo + base + 8*SM_STRIDE];
                ah[mt][2] = *(const uint32_t*)&sm[AHo + base + 8];
                ah[mt][3] = *(const uint32_t*)&sm[AHo + base + 8*SM_STRIDE + 8];
                al[mt][0] = *(const uint32_t*)&sm[ALo + base];
                al[mt][1] = *(const uint32_t*)&sm[ALo + base + 8*SM_STRIDE];
                al[mt][2] = *(const uint32_t*)&sm[ALo + base + 8];
                al[mt][3] = *(const uint32_t*)&sm[ALo + base + 8*SM_STRIDE + 8];
            }
            uint32_t bh[8][2], bl[8][2];
            #pragma unroll
            for (int nt = 0; nt < 8; nt++) {
                int base = (wn + nt*8 + (lane >> 2)) * SM_STRIDE + ks + (lane & 3) * 2;
                bh[nt][0] = *(const uint32_t*)&sm[BHo + base];
                bh[nt][1] = *(const uint32_t*)&sm[BHo + base + 8];
                bl[nt][0] = *(const uint32_t*)&sm[BLo + base];
                bl[nt][1] = *(const uint32_t*)&sm[BLo + base + 8];
            }
            #pragma unroll
            for (int mt = 0; mt < 2; mt++)
                #pragma unroll
                for (int nt = 0; nt < 8; nt++) {
                    mma16816(acc[mt][nt], ah[mt], bh[nt]);
                    mma16816(acc[mt][nt], ah[mt], bl[nt]);
                    mma16816(acc[mt][nt], al[mt], bh[nt]);
                }
        }
        __syncthreads();
        if (kb + 1 < nk) {
            #pragma unroll
            for (int rr = 0; rr < 16; rr++) {
                __half h, l; split2(pa[rr], h, l);
                sm[AHo + (w*16+rr)*SM_STRIDE + lane] = h;
                sm[ALo + (w*16+rr)*SM_STRIDE + lane] = l;
            }
            #pragma unroll
            for (int i = 0; i < 4; i++) {
                int k = 8*i + w;
                #pragma unroll
                for (int j = 0; j < 4; j++) {
                    int nl = lane + 32*j;
                    __half h, l; split2(pb[i*4+j], h, l);
                    sm[BHo + nl*SM_STRIDE + k] = h;
                    sm[BLo + nl*SM_STRIDE + k] = l;
                }
            }
            __syncthreads();
        }
    }

    #pragma unroll
    for (int mt = 0; mt < 2; mt++) {
        #pragma unroll
        for (int nt = 0; nt < 8; nt++) {
            int col = n0 + wn + nt*8 + (lane & 3) * 2;
            float b0 = bias[col], b1 = bias[col+1];
            int r0 = m0 + wm + mt*16 + (lane >> 2);
            if (r0 < Md) {
                float2 o;
                o.x = fmaxf(acc[mt][nt][0] + b0, 0.f);
                o.y = fmaxf(acc[mt][nt][1] + b1, 0.f);
                *(float2*)(Cm + (size_t)r0 * DTd + col) = o;
            }
            int r1 = r0 + 8;
            if (r1 < Md) {
                float2 o;
                o.x = fmaxf(acc[mt][nt][2] + b0, 0.f);
                o.y = fmaxf(acc[mt][nt][3] + b1, 0.f);
                *(float2*)(Cm + (size_t)r1 * DTd + col) = o;
            }
        }
    }
}

// ---------------- top-k (matches jax.lax.top_k: ties -> lowest index) -----
__global__ void topk_kernel(const float* __restrict__ logits) {
    int b = blockIdx.x;
    const float* row = logits + b*Cd;
    __shared__ float sv[256];
    __shared__ int   si[256];
    __shared__ int   chosen[TK];
    int tid = threadIdx.x;
    for (int sel = 0; sel < TK; sel++) {
        float best = -INFINITY; int bi = 1 << 30;
        for (int i = tid; i < Cd; i += 256) {
            bool skip = false;
            for (int j = 0; j < sel; j++) if (chosen[j] == i) skip = true;
            if (skip) continue;
            float v = row[i];
            if (v > best || (v == best && i < bi)) { best = v; bi = i; }
        }
        sv[tid] = best; si[tid] = bi;
        __syncthreads();
        for (int s = 128; s > 0; s >>= 1) {
            if (tid < s) {
                if (sv[tid+s] > sv[tid] || (sv[tid+s] == sv[tid] && si[tid+s] < si[tid])) {
                    sv[tid] = sv[tid+s]; si[tid] = si[tid+s];
                }
            }
            __syncthreads();
        }
        if (tid == 0) chosen[sel] = si[0];
        __syncthreads();
    }
    if (tid < TK) g_topk[b*TK + tid] = chosen[tid];
}

// ---------------- gather + mean-pool word embeddings -----------------------
__global__ void gather_emb_kernel(const int* __restrict__ table,
                                  const float* __restrict__ w2v) {
    int bk = blockIdx.x;
    int c  = g_topk[bk];
    int i0 = table[c*4+0], i1 = table[c*4+1], i2 = table[c*4+2], i3 = table[c*4+3];
    for (int d = threadIdx.x; d < DWd; d += blockDim.x)
        g_emb[bk*DWd + d] = 0.25f*(w2v[(size_t)i0*DWd+d] + w2v[(size_t)i1*DWd+d]
                                 + w2v[(size_t)i2*DWd+d] + w2v[(size_t)i3*DWd+d]);
}

// ========== fused attention: scores + softmax + bap, one CTA per batch =====
// smem: cls_s [10*1024] floats (40960 B) + att_s [676*12] floats (32448 B)
#define ASMEM ((TK*DTd + Fd*12) * 4)

__global__ void __launch_bounds__(512)
attn_kernel() {
    extern __shared__ float smf[];
    float* cls_s = smf;               // [TK*DTd]
    float* att_s = smf + TK*DTd;      // [Fd*12]
    int b   = blockIdx.x;
    int tid = threadIdx.x;
    int w   = tid >> 5, lane = tid & 31;

    for (int i = tid; i < TK*DTd; i += 512)
        cls_s[i] = g_cls[b*TK*DTd + i];
    for (int i = tid; i < Fd*12; i += 512)
        att_s[i] = 0.f;
    __syncthreads();

    const float* vb = g_v + (size_t)b*Fd*DTd;

    // ---- scores: warp handles f-groups of 8 (same math as scores_kernel) --
    for (int g = w; g * 8 < Fd; g += 16) {
        int f0 = g * 8;
        float acc[8][TK];
        #pragma unroll
        for (int j = 0; j < 8; j++)
            #pragma unroll
            for (int k = 0; k < TK; k++) acc[j][k] = 0.f;
        for (int i = 0; i < 32; i++) {
            int t = lane + 32*i;
            float c[TK];
            #pragma unroll
            for (int k = 0; k < TK; k++) c[k] = cls_s[k*DTd + t];
            #pragma unroll
            for (int j = 0; j < 8; j++) {
                float vv = (f0+j < Fd) ? vb[(size_t)(f0+j)*DTd + t] : 0.f;
                #pragma unroll
                for (int k = 0; k < TK; k++) acc[j][k] += vv * c[k];
            }
        }
        #pragma unroll
        for (int j = 0; j < 8; j++) {
            #pragma unroll
            for (int k = 0; k < TK; k++) {
                float r = acc[j][k];
                #pragma unroll
                for (int o = 16; o; o >>= 1) r += __shfl_xor_sync(0xffffffffu, r, o);
                if (lane == 0 && f0+j < Fd)
                    att_s[(f0+j)*12 + k] = r;
            }
        }
    }
    __syncthreads();

    // ---- softmax over f per k (warp k, lanes stride f by 32: R12 order) ---
    if (w < TK) {
        int k = w;
        float m = -INFINITY;
        for (int f = lane; f < Fd; f += 32) m = fmaxf(m, att_s[f*12 + k]);
        #pragma unroll
        for (int o = 16; o; o >>= 1) m = fmaxf(m, __shfl_xor_sync(0xffffffffu, m, o));
        float s = 0.f;
        for (int f = lane; f < Fd; f += 32) {
            float e = expf(att_s[f*12 + k] - m);
            att_s[f*12 + k] = e;
            s += e;
        }
        #pragma unroll
        for (int o = 16; o; o >>= 1) s += __shfl_xor_sync(0xffffffffu, s, o);
        float inv = 1.f / s;
        for (int f = lane; f < Fd; f += 32) att_s[f*12 + k] *= inv;
    }
    __syncthreads();

    // ---- bap: each thread owns d and d+512 (same per-d f-order as before) -
    {
        float acc0[TK] = {}, acc1[TK] = {};
        const float* v0 = vb + tid;
        const float* v1 = vb + tid + 512;
        #pragma unroll 4
        for (int f = 0; f < Fd; f++) {
            float vv0 = v0[(size_t)f*DTd];
            float vv1 = v1[(size_t)f*DTd];
            const float4* ap = (const float4*)&att_s[f*12];
            float4 a0 = ap[0], a1 = ap[1], a2 = ap[2];
            acc0[0] += vv0*a0.x; acc0[1] += vv0*a0.y; acc0[2] += vv0*a0.z; acc0[3] += vv0*a0.w;
            acc0[4] += vv0*a1.x; acc0[5] += vv0*a1.y; acc0[6] += vv0*a1.z; acc0[7] += vv0*a1.w;
            acc0[8] += vv0*a2.x; acc0[9] += vv0*a2.y;
            acc1[0] += vv1*a0.x; acc1[1] += vv1*a0.y; acc1[2] += vv1*a0.z; acc1[3] += vv1*a0.w;
            acc1[4] += vv1*a1.x; acc1[5] += vv1*a1.y; acc1[6] += vv1*a1.z; acc1[7] += vv1*a1.w;
            acc1[8] += vv1*a2.x; acc1[9] += vv1*a2.y;
        }
        float r0 = 0.f, r1 = 0.f;
        #pragma unroll
        for (int k = 0; k < TK; k++) {
            r0 += acc0[k] * cls_s[k*DTd + tid];
            r1 += acc1[k] * cls_s[k*DTd + tid + 512];
        }
        g_bap[b*DTd + tid]       = r0;
        g_bap[b*DTd + tid + 512] = r1;
    }
}

// -------- bap2 = relu(bap @ W_bap + b_bap) ---------------------------------
__global__ void fcw_kernel(const float* __restrict__ Wb, const float* __restrict__ bb) {
    __shared__ float row[DTd];
    int m = blockIdx.x >> 2;
    int n = (blockIdx.x & 3) * 256 + threadIdx.x;
    #pragma unroll
    for (int i = 0; i < 4; i++)
        row[threadIdx.x + i*256] = g_bap[m*DTd + threadIdx.x + i*256];
    __syncthreads();
    float acc = 0.f;
    #pragma unroll 8
    for (int d = 0; d < DTd; d++)
        acc += row[d] * Wb[(size_t)d*DTd + n];
    g_bap2[m*DTd + n] = fmaxf(acc + bb[n], 0.f);
}

// ---------------- final FC (DT->K) + scatter into [B, C] output ------------
__global__ void fc_scatter_kernel(const float* __restrict__ W_fc,
                                  const float* __restrict__ b_fc,
                                  float* __restrict__ out) {
    int b = blockIdx.x;
    int wid = threadIdx.x >> 5, lane = threadIdx.x & 31;
    if (wid < TK) {
        float s = 0.f;
        for (int d = lane; d < DTd; d += 32)
            s += g_bap2[b*DTd + d] * W_fc[d*TK + wid];
        #pragma unroll
        for (int o = 16; o; o >>= 1) s += __shfl_xor_sync(0xffffffffu, s, o);
        if (lane == 0)
            out[(size_t)b*Cd + g_topk[b*TK + wid]] = s + b_fc[wid];
    }
}

// ---------------- launch ----------------------------------------------------
extern "C" void kernel_launch(void* const* d_in, const int* in_sizes, int n_in,
                              void* d_out, int out_size) {
    const float* ftm    = (const float*)d_in[0];
    const float* logits = (const float*)d_in[1];
    const int*   table  = (const int*)  d_in[3];
    const float* w2v    = (const float*)d_in[4];
    const float* W_emb  = (const float*)d_in[5];
    const float* b_emb  = (const float*)d_in[6];
    const float* W_cls  = (const float*)d_in[7];
    const float* b_cls  = (const float*)d_in[8];
    const float* W_v    = (const float*)d_in[9];
    const float* b_v    = (const float*)d_in[10];
    const float* W_bap  = (const float*)d_in[11];
    const float* b_bap  = (const float*)d_in[12];
    const float* W_fc   = (const float*)d_in[13];
    const float* b_fc   = (const float*)d_in[14];
    float* out = (float*)d_out;

    float *p_emb, *p_cls1, *p_cls, *p_v;
    cudaGetSymbolAddress((void**)&p_emb,  g_emb);
    cudaGetSymbolAddress((void**)&p_cls1, g_cls1);
    cudaGetSymbolAddress((void**)&p_cls,  g_cls);
    cudaGetSymbolAddress((void**)&p_v,    g_v);

    cudaFuncSetAttribute(vgemm5_kernel, cudaFuncAttributeMaxDynamicSharedMemorySize, VSMEM5);
    cudaFuncSetAttribute(attn_kernel,   cudaFuncAttributeMaxDynamicSharedMemorySize, ASMEM);

    cudaStream_t s2;
    cudaEvent_t evF, evJ;
    cudaStreamCreateWithFlags(&s2, cudaStreamNonBlocking);
    cudaEventCreateWithFlags(&evF, cudaEventDisableTiming);
    cudaEventCreateWithFlags(&evJ, cudaEventDisableTiming);

    cudaMemsetAsync(d_out, 0, (size_t)out_size * sizeof(float), 0);
    cudaEventRecord(evF, 0);
    cudaStreamWaitEvent(s2, evF, 0);

    // memset(1) -> topk(2,s2) -> gather(3,s2) -> convW(4) -> vgemm5(5: ncu -s 5)
    topk_kernel<<<Bsz, 256, 0, s2>>>(logits);
    gather_emb_kernel<<<Bsz*TK, 128, 0, s2>>>(table, w2v);

    convW_kernel<<<dim3(32, 24), 256>>>(W_v);
    vgemm5_kernel<<<dim3(8, 6, Bsz), 256, VSMEM5>>>(ftm, b_v, p_v);

    // side stream: cls GEMMs hidden under the v-GEMM
    tgemm_kernel<<<dim3(8, 5, 1), 256, 0, s2>>>(p_emb,  W_emb, b_emb, p_cls1, Bsz*TK, DWd);
    tgemm_kernel<<<dim3(8, 5, 1), 256, 0, s2>>>(p_cls1, W_cls, b_cls, p_cls,  Bsz*TK, DTd);
    cudaEventRecord(evJ, s2);
    cudaStreamWaitEvent(0, evJ, 0);

    attn_kernel<<<Bsz, 512, ASMEM>>>();
    fcw_kernel  <<<Bsz*4, 256>>>(W_bap, b_bap);
    fc_scatter_kernel<<<Bsz, 320>>>(W_fc, b_fc, out);
}

// round 17
// speedup vs baseline: 1.1852x; 1.1852x over previous
#include <cuda_runtime.h>
#include <cuda_fp16.h>
#include <math.h>
#include <stdint.h>

#define Bsz 64
#define DFd 768
#define Fd  676
#define Cd  3129
#define DWd 300
#define DTd 1024
#define TK  10

// ---------------- device scratch (static, allocation-free) ----------------
__device__ int    g_topk[Bsz*TK];
__device__ float  g_emb [Bsz*TK*DWd];
__device__ float  g_cls1[Bsz*TK*DTd];
__device__ float  g_cls [Bsz*TK*DTd];
__device__ float  g_v   [(size_t)Bsz*Fd*DTd];   // 177 MB
__device__ float  g_s   [Bsz*Fd*TK];
__device__ float  g_bap [Bsz*DTd];
__device__ float  g_bap2[Bsz*DTd];
__device__ __half g_wh[DTd*DFd];                // W^T hi [n][k]
__device__ __half g_wl[DTd*DFd];                // W^T lo [n][k]

__device__ __forceinline__ void mma16816(float* c, const uint32_t* a, const uint32_t* b) {
    asm volatile(
        "mma.sync.aligned.m16n8k16.row.col.f32.f16.f16.f32 "
        "{%0,%1,%2,%3}, {%4,%5,%6,%7}, {%8,%9}, {%0,%1,%2,%3};"
        : "+f"(c[0]), "+f"(c[1]), "+f"(c[2]), "+f"(c[3])
        : "r"(a[0]), "r"(a[1]), "r"(a[2]), "r"(a[3]), "r"(b[0]), "r"(b[1]));
}
#define LDSM4(r0,r1,r2,r3,addr) \
    asm volatile("ldmatrix.sync.aligned.m8n8.x4.shared.b16 {%0,%1,%2,%3}, [%4];" \
                 : "=r"(r0), "=r"(r1), "=r"(r2), "=r"(r3) : "r"(addr))
__device__ __forceinline__ void split2(float x, __half& h, __half& l) {
    h = __float2half_rn(x);
    l = __float2half_rn(x - __half2float(h));
}
__device__ __forceinline__ uint32_t pk2(__half a, __half b) {
    __half2 t = __halves2half2(a, b);
    return *(uint32_t*)&t;
}
__device__ __forceinline__ void cp16(uint32_t dst, const void* src, int nbytes) {
    asm volatile("cp.async.cg.shared.global [%0], [%1], 16, %2;"
                 :: "r"(dst), "l"(src), "r"(nbytes));
}
__device__ __forceinline__ uint32_t smem_u32(const void* p) {
    uint32_t a;
    asm("{ .reg .u64 t; cvta.to.shared.u64 t, %1; cvt.u32.u64 %0, t; }" : "=r"(a) : "l"(p));
    return a;
}

// ============ W preconvert: W_v [k][n] -> g_wh/g_wl [n][k] =================
__global__ void convW_kernel(const float* __restrict__ Wv) {
    __shared__ float tile[32][33];
    int n0 = blockIdx.x * 32, k0 = blockIdx.y * 32;
    int tx = threadIdx.x & 31, ty = threadIdx.x >> 5;
    #pragma unroll
    for (int j = 0; j < 4; j++)
        tile[ty + j*8][tx] = Wv[(size_t)(k0 + ty + j*8) * DTd + n0 + tx];
    __syncthreads();
    #pragma unroll
    for (int j = 0; j < 4; j++) {
        int n = n0 + ty + j*8, k = k0 + tx;
        __half h, l; split2(tile[tx][ty + j*8], h, l);
        size_t o = (size_t)n * DFd + k;
        g_wh[o] = h; g_wl[o] = l;
    }
}

// ============ v-GEMM v5: A fp32-staged + in-smem convert, ldmatrix HMMA ===
#define AH_IX 0
#define AL_IX 5120          // halves
#define A_HST 40
#define B_ST  40
#define B_BASE   20480
#define B_STAGEB 20480
#define A_BASE   61440
#define A_STAGEB 16896
#define VSMEM5   95232

__global__ void __launch_bounds__(256, 2)
vgemm5_kernel(const float* __restrict__ ftm, const float* __restrict__ bias,
              float* __restrict__ outv, int b_base)
{
    extern __shared__ char smraw[];
    __half* smh = (__half*)smraw;
    int tid  = threadIdx.x;
    int w    = tid >> 5, lane = tid & 31;
    int b    = b_base + blockIdx.z;
    int m0   = blockIdx.y * 128, n0 = blockIdx.x * 128;
    uint32_t smb = smem_u32(smraw);

    const float* Ab = ftm + (size_t)b * DFd * Fd;

    auto fill = [&](int s, int k0) {
        uint32_t abase = smb + A_BASE + (uint32_t)s * A_STAGEB;
        uint32_t bbase = smb + B_BASE + (uint32_t)s * B_STAGEB;
        #pragma unroll
        for (int i = 0; i < 8; i++) {
            int idx = tid + i * 256;
            if (idx < 1024) {                    // A fp32 [32k][132f]
                int k = idx >> 5, c = idx & 31;
                uint32_t dst = abase + (uint32_t)(k * 132 + c * 4) * 4;
                int nb = (m0 + c * 4 + 4 <= Fd) ? 16 : 0;
                const float* src = Ab + (size_t)(k0 + k) * Fd + (nb ? (m0 + c * 4) : 0);
                cp16(dst, src, nb);
            } else {                             // B halves [128n][40k] x2 limbs
                int j = idx - 1024;
                int limb = j >> 9, wi = j & 511;
                int n = wi >> 2, c = wi & 3;
                const __half* src = (limb ? g_wl : g_wh) + (size_t)(n0 + n) * DFd + k0 + c * 8;
                uint32_t dst = bbase + (uint32_t)(limb * 5120 + n * B_ST + c * 8) * 2;
                cp16(dst, src, 16);
            }
        }
        asm volatile("cp.async.commit_group;" ::: "memory");
    };

    fill(0, 0);

    int wm = (w & 3) * 32;
    int wn = (w >> 2) * 64;
    bool mma_active = (m0 + wm) < Fd;

    int aOff = (wm + (lane & 15)) * A_HST + (lane >> 4) * 8;
    int bOff = (wn + ((lane >> 4) & 1) * 8 + (lane & 7)) * B_ST + ((lane >> 3) & 1) * 8;
    int cf  = (w & 3) * 32 + lane;
    int cc0 = (w >> 2) * 2;

    float acc[2][8][4];
    #pragma unroll
    for (int mt = 0; mt < 2; mt++)
        #pragma unroll
        for (int nt = 0; nt < 8; nt++)
            #pragma unroll
            for (int q = 0; q < 4; q++) acc[mt][nt][q] = 0.f;

    const int NK = DFd / 32;    // 24
    for (int kb = 0; kb < NK; kb++) {
        if (kb + 1 < NK) {
            fill((kb + 1) & 1, (kb + 1) * 32);
            asm volatile("cp.async.wait_group 1;" ::: "memory");
        } else {
            asm volatile("cp.async.wait_group 0;" ::: "memory");
        }
        __syncthreads();
        {
            const float* sA = (const float*)(smraw + A_BASE + (size_t)(kb & 1) * A_STAGEB);
            #pragma unroll
            for (int ci = 0; ci < 2; ci++) {
                int c = cc0 + ci;
                float v[8];
                #pragma unroll
                for (int j = 0; j < 8; j++)
                    v[j] = sA[(c * 8 + j) * 132 + cf];
                uint32_t hh[4], ll[4];
                #pragma unroll
                for (int j = 0; j < 4; j++) {
                    __half h0, l0, h1, l1;
                    split2(v[2*j],   h0, l0);
                    split2(v[2*j+1], h1, l1);
                    hh[j] = pk2(h0, h1);
                    ll[j] = pk2(l0, l1);
                }
                *(uint4*)&smh[AH_IX + cf * A_HST + c * 8] = make_uint4(hh[0], hh[1], hh[2], hh[3]);
                *(uint4*)&smh[AL_IX + cf * A_HST + c * 8] = make_uint4(ll[0], ll[1], ll[2], ll[3]);
            }
        }
        __syncthreads();
        if (mma_active) {
            uint32_t bstage = smb + B_BASE + (uint32_t)(kb & 1) * B_STAGEB;
            #pragma unroll
            for (int ks = 0; ks < 32; ks += 16) {
                uint32_t ah[2][4], al[2][4];
                #pragma unroll
                for (int mt = 0; mt < 2; mt++) {
                    LDSM4(ah[mt][0], ah[mt][1], ah[mt][2], ah[mt][3],
                          smb + (uint32_t)(AH_IX + aOff + mt * 16 * A_HST + ks) * 2);
                    LDSM4(al[mt][0], al[mt][1], al[mt][2], al[mt][3],
                          smb + (uint32_t)(AL_IX + aOff + mt * 16 * A_HST + ks) * 2);
                }
                uint32_t bh[8][2], bl[8][2];
                #pragma unroll
                for (int p = 0; p < 4; p++) {
                    LDSM4(bh[2*p][0], bh[2*p][1], bh[2*p+1][0], bh[2*p+1][1],
                          bstage + (uint32_t)(bOff + p * 16 * B_ST + ks) * 2);
                    LDSM4(bl[2*p][0], bl[2*p][1], bl[2*p+1][0], bl[2*p+1][1],
                          bstage + (uint32_t)(5120 + bOff + p * 16 * B_ST + ks) * 2);
                }
                #pragma unroll
                for (int mt = 0; mt < 2; mt++)
                    #pragma unroll
                    for (int nt = 0; nt < 8; nt++) {
                        mma16816(acc[mt][nt], ah[mt], bh[nt]);
                        mma16816(acc[mt][nt], ah[mt], bl[nt]);
                        mma16816(acc[mt][nt], al[mt], bh[nt]);
                    }
            }
        }
        __syncthreads();
    }

    float* Cb = outv + (size_t)b * Fd * DTd;
    #pragma unroll
    for (int mt = 0; mt < 2; mt++) {
        #pragma unroll
        for (int nt = 0; nt < 8; nt++) {
            int col = n0 + wn + nt*8 + (lane & 3) * 2;
            float b0 = bias[col], b1 = bias[col+1];
            int r0 = m0 + wm + mt*16 + (lane >> 2);
            if (r0 < Fd) {
                float2 o;
                o.x = fmaxf(acc[mt][nt][0] + b0, 0.f);
                o.y = fmaxf(acc[mt][nt][1] + b1, 0.f);
                *(float2*)(Cb + (size_t)r0 * DTd + col) = o;
            }
            int r1 = r0 + 8;
            if (r1 < Fd) {
                float2 o;
                o.x = fmaxf(acc[mt][nt][2] + b0, 0.f);
                o.y = fmaxf(acc[mt][nt][3] + b1, 0.f);
                *(float2*)(Cb + (size_t)r1 * DTd + col) = o;
            }
        }
    }
}

// ================= fp16x2-split GEMM for cls ===============================
#define SM_STRIDE 34
#define AHo 0
#define ALo (128*SM_STRIDE)
#define BHo (2*128*SM_STRIDE)
#define BLo (3*128*SM_STRIDE)

__global__ void __launch_bounds__(256)
tgemm_kernel(const float* __restrict__ A, const float* __restrict__ Bm,
             const float* __restrict__ bias, float* __restrict__ Cm,
             int Md, int Kd)
{
    __shared__ __half sm[4*128*SM_STRIDE];
    int tid  = threadIdx.x;
    int w    = tid >> 5, lane = tid & 31;
    int m0   = blockIdx.y * 128, n0 = blockIdx.x * 128;
    int nk = (Kd + 31) / 32;

    float pa[16], pb[16];
    {
        int k0 = 0;
        #pragma unroll
        for (int rr = 0; rr < 16; rr++) {
            int m = m0 + w*16 + rr;
            pa[rr] = (m < Md && k0+lane < Kd) ? A[(size_t)m*Kd + k0 + lane] : 0.f;
        }
        #pragma unroll
        for (int i = 0; i < 4; i++) {
            int k = 8*i + w;
            const float* col = Bm + (size_t)(k0 + k) * DTd + n0;
            #pragma unroll
            for (int j = 0; j < 4; j++)
                pb[i*4+j] = (k0+k < Kd) ? col[lane + 32*j] : 0.f;
        }
    }
    {
        #pragma unroll
        for (int rr = 0; rr < 16; rr++) {
            __half h, l; split2(pa[rr], h, l);
            sm[AHo + (w*16+rr)*SM_STRIDE + lane] = h;
            sm[ALo + (w*16+rr)*SM_STRIDE + lane] = l;
        }
        #pragma unroll
        for (int i = 0; i < 4; i++) {
            int k = 8*i + w;
            #pragma unroll
            for (int j = 0; j < 4; j++) {
                int nl = lane + 32*j;
                __half h, l; split2(pb[i*4+j], h, l);
                sm[BHo + nl*SM_STRIDE + k] = h;
                sm[BLo + nl*SM_STRIDE + k] = l;
            }
        }
    }
    __syncthreads();

    int wm = (w & 3) * 32;
    int wn = (w >> 2) * 64;
    float acc[2][8][4];
    #pragma unroll
    for (int mt = 0; mt < 2; mt++)
        #pragma unroll
        for (int nt = 0; nt < 8; nt++)
            #pragma unroll
            for (int q = 0; q < 4; q++) acc[mt][nt][q] = 0.f;

    for (int kb = 0; kb < nk; kb++) {
        if (kb + 1 < nk) {
            int k0 = (kb + 1) * 32;
            #pragma unroll
            for (int rr = 0; rr < 16; rr++) {
                int m = m0 + w*16 + rr;
                pa[rr] = (m < Md && k0+lane < Kd) ? A[(size_t)m*Kd + k0 + lane] : 0.f;
            }
            #pragma unroll
            for (int i = 0; i < 4; i++) {
                int k = 8*i + w;
                const float* col = Bm + (size_t)(k0 + k) * DTd + n0;
                #pragma unroll
                for (int j = 0; j < 4; j++)
                    pb[i*4+j] = (k0+k < Kd) ? col[lane + 32*j] : 0.f;
            }
        }
        #pragma unroll
        for (int ks = 0; ks < 32; ks += 16) {
            uint32_t ah[2][4], al[2][4];
            #pragma unroll
            for (int mt = 0; mt < 2; mt++) {
                int base = (wm + mt*16 + (lane >> 2)) * SM_STRIDE + ks + (lane & 3) * 2;
                ah[mt][0] = *(const uint32_t*)&sm[AHo + base];
                ah[mt][1] = *(const uint32_t*)&sm[AHo + base + 8*SM_STRIDE];
                ah[mt][2] = *(const uint32_t*)&sm[AHo + base + 8];
                ah[mt][3] = *(const uint32_t*)&sm[AHo + base + 8*SM_STRIDE + 8];
                al[mt][0] = *(const uint32_t*)&sm[ALo + base];
                al[mt][1] = *(const uint32_t*)&sm[ALo + base + 8*SM_STRIDE];
                al[mt][2] = *(const uint32_t*)&sm[ALo + base + 8];
                al[mt][3] = *(const uint32_t*)&sm[ALo + base + 8*SM_STRIDE + 8];
            }
            uint32_t bh[8][2], bl[8][2];
            #pragma unroll
            for (int nt = 0; nt < 8; nt++) {
                int base = (wn + nt*8 + (lane >> 2)) * SM_STRIDE + ks + (lane & 3) * 2;
                bh[nt][0] = *(const uint32_t*)&sm[BHo + base];
                bh[nt][1] = *(const uint32_t*)&sm[BHo + base + 8];
                bl[nt][0] = *(const uint32_t*)&sm[BLo + base];
                bl[nt][1] = *(const uint32_t*)&sm[BLo + base + 8];
            }
            #pragma unroll
            for (int mt = 0; mt < 2; mt++)
                #pragma unroll
                for (int nt = 0; nt < 8; nt++) {
                    mma16816(acc[mt][nt], ah[mt], bh[nt]);
                    mma16816(acc[mt][nt], ah[mt], bl[nt]);
                    mma16816(acc[mt][nt], al[mt], bh[nt]);
                }
        }
        __syncthreads();
        if (kb + 1 < nk) {
            #pragma unroll
            for (int rr = 0; rr < 16; rr++) {
                __half h, l; split2(pa[rr], h, l);
                sm[AHo + (w*16+rr)*SM_STRIDE + lane] = h;
                sm[ALo + (w*16+rr)*SM_STRIDE + lane] = l;
            }
            #pragma unroll
            for (int i = 0; i < 4; i++) {
                int k = 8*i + w;
                #pragma unroll
                for (int j = 0; j < 4; j++) {
                    int nl = lane + 32*j;
                    __half h, l; split2(pb[i*4+j], h, l);
                    sm[BHo + nl*SM_STRIDE + k] = h;
                    sm[BLo + nl*SM_STRIDE + k] = l;
                }
            }
            __syncthreads();
        }
    }

    #pragma unroll
    for (int mt = 0; mt < 2; mt++) {
        #pragma unroll
        for (int nt = 0; nt < 8; nt++) {
            int col = n0 + wn + nt*8 + (lane & 3) * 2;
            float b0 = bias[col], b1 = bias[col+1];
            int r0 = m0 + wm + mt*16 + (lane >> 2);
            if (r0 < Md) {
                float2 o;
                o.x = fmaxf(acc[mt][nt][0] + b0, 0.f);
                o.y = fmaxf(acc[mt][nt][1] + b1, 0.f);
                *(float2*)(Cm + (size_t)r0 * DTd + col) = o;
            }
            int r1 = r0 + 8;
            if (r1 < Md) {
                float2 o;
                o.x = fmaxf(acc[mt][nt][2] + b0, 0.f);
                o.y = fmaxf(acc[mt][nt][3] + b1, 0.f);
                *(float2*)(Cm + (size_t)r1 * DTd + col) = o;
            }
        }
    }
}

// ---------------- top-k (matches jax.lax.top_k: ties -> lowest index) -----
__global__ void topk_kernel(const float* __restrict__ logits) {
    int b = blockIdx.x;
    const float* row = logits + b*Cd;
    __shared__ float sv[256];
    __shared__ int   si[256];
    __shared__ int   chosen[TK];
    int tid = threadIdx.x;
    for (int sel = 0; sel < TK; sel++) {
        float best = -INFINITY; int bi = 1 << 30;
        for (int i = tid; i < Cd; i += 256) {
            bool skip = false;
            for (int j = 0; j < sel; j++) if (chosen[j] == i) skip = true;
            if (skip) continue;
            float v = row[i];
            if (v > best || (v == best && i < bi)) { best = v; bi = i; }
        }
        sv[tid] = best; si[tid] = bi;
        __syncthreads();
        for (int s = 128; s > 0; s >>= 1) {
            if (tid < s) {
                if (sv[tid+s] > sv[tid] || (sv[tid+s] == sv[tid] && si[tid+s] < si[tid])) {
                    sv[tid] = sv[tid+s]; si[tid] = si[tid+s];
                }
            }
            __syncthreads();
        }
        if (tid == 0) chosen[sel] = si[0];
        __syncthreads();
    }
    if (tid < TK) g_topk[b*TK + tid] = chosen[tid];
}

// ---------------- gather + mean-pool word embeddings -----------------------
__global__ void gather_emb_kernel(const int* __restrict__ table,
                                  const float* __restrict__ w2v) {
    int bk = blockIdx.x;
    int c  = g_topk[bk];
    int i0 = table[c*4+0], i1 = table[c*4+1], i2 = table[c*4+2], i3 = table[c*4+3];
    for (int d = threadIdx.x; d < DWd; d += blockDim.x)
        g_emb[bk*DWd + d] = 0.25f*(w2v[(size_t)i0*DWd+d] + w2v[(size_t)i1*DWd+d]
                                 + w2v[(size_t)i2*DWd+d] + w2v[(size_t)i3*DWd+d]);
}

// ---------------- attention scores (batch slice): b = b0 + blockIdx.y ------
__global__ void scores_kernel(int b0) {
    int b = b0 + blockIdx.y;
    __shared__ float cls_s[TK*DTd];
    for (int i = threadIdx.x; i < TK*DTd; i += 256)
        cls_s[i] = g_cls[b*TK*DTd + i];
    __syncthreads();
    int w = threadIdx.x >> 5, lane = threadIdx.x & 31;
    int f0 = (blockIdx.x*8 + w) * 8;
    float acc[8][TK];
    #pragma unroll
    for (int j = 0; j < 8; j++)
        #pragma unroll
        for (int k = 0; k < TK; k++) acc[j][k] = 0.f;
    const float* vb = g_v + (size_t)b*Fd*DTd;
    for (int i = 0; i < 32; i++) {
        int t = lane + 32*i;
        float c[TK];
        #pragma unroll
        for (int k = 0; k < TK; k++) c[k] = cls_s[k*DTd + t];
        #pragma unroll
        for (int j = 0; j < 8; j++) {
            float vv = (f0+j < Fd) ? vb[(size_t)(f0+j)*DTd + t] : 0.f;
            #pragma unroll
            for (int k = 0; k < TK; k++) acc[j][k] += vv * c[k];
        }
    }
    #pragma unroll
    for (int j = 0; j < 8; j++) {
        #pragma unroll
        for (int k = 0; k < TK; k++) {
            float r = acc[j][k];
            #pragma unroll
            for (int o = 16; o; o >>= 1) r += __shfl_xor_sync(0xffffffffu, r, o);
            if (lane == 0 && f0+j < Fd)
                g_s[((size_t)b*Fd + f0 + j)*TK + k] = r;
        }
    }
}

// -------- bap with fused softmax (batch slice) -----------------------------
__global__ void bap_kernel(int b0) {
    int b = b0 + blockIdx.y;
    int d = blockIdx.x*256 + threadIdx.x;
    int w = threadIdx.x >> 5, lane = threadIdx.x & 31;
    __shared__ float att_s[Fd*12];
    for (int i = threadIdx.x; i < Fd*12; i += 256) {
        int f = i / 12, k = i % 12;
        att_s[i] = (k < TK) ? g_s[((size_t)b*Fd + f)*TK + k] : 0.f;
    }
    __syncthreads();
    for (int k = w; k < TK; k += 8) {
        float m = -INFINITY;
        for (int f = lane; f < Fd; f += 32) m = fmaxf(m, att_s[f*12 + k]);
        #pragma unroll
        for (int o = 16; o; o >>= 1) m = fmaxf(m, __shfl_xor_sync(0xffffffffu, m, o));
        float s = 0.f;
        for (int f = lane; f < Fd; f += 32) {
            float e = expf(att_s[f*12 + k] - m);
            att_s[f*12 + k] = e;
            s += e;
        }
        #pragma unroll
        for (int o = 16; o; o >>= 1) s += __shfl_xor_sync(0xffffffffu, s, o);
        float inv = 1.f / s;
        for (int f = lane; f < Fd; f += 32) att_s[f*12 + k] *= inv;
    }
    __syncthreads();
    float acc[TK] = {};
    const float* vb = g_v + (size_t)b*Fd*DTd + d;
    #pragma unroll 4
    for (int f = 0; f < Fd; f++) {
        float vv = vb[(size_t)f*DTd];
        const float4* ap = (const float4*)&att_s[f*12];
        float4 a0 = ap[0], a1 = ap[1], a2 = ap[2];
        acc[0] += vv*a0.x; acc[1] += vv*a0.y; acc[2] += vv*a0.z; acc[3] += vv*a0.w;
        acc[4] += vv*a1.x; acc[5] += vv*a1.y; acc[6] += vv*a1.z; acc[7] += vv*a1.w;
        acc[8] += vv*a2.x; acc[9] += vv*a2.y;
    }
    float r = 0.f;
    #pragma unroll
    for (int k = 0; k < TK; k++)
        r += acc[k] * g_cls[((size_t)b*TK + k)*DTd + d];
    g_bap[b*DTd + d] = r;
}

// -------- bap2 = relu(bap @ W_bap + b_bap) ---------------------------------
__global__ void fcw_kernel(const float* __restrict__ Wb, const float* __restrict__ bb) {
    __shared__ float row[DTd];
    int m = blockIdx.x >> 2;
    int n = (blockIdx.x & 3) * 256 + threadIdx.x;
    #pragma unroll
    for (int i = 0; i < 4; i++)
        row[threadIdx.x + i*256] = g_bap[m*DTd + threadIdx.x + i*256];
    __syncthreads();
    float acc = 0.f;
    #pragma unroll 8
    for (int d = 0; d < DTd; d++)
        acc += row[d] * Wb[(size_t)d*DTd + n];
    g_bap2[m*DTd + n] = fmaxf(acc + bb[n], 0.f);
}

// ---------------- final FC (DT->K) + scatter into [B, C] output ------------
__global__ void fc_scatter_kernel(const float* __restrict__ W_fc,
                                  const float* __restrict__ b_fc,
                                  float* __restrict__ out) {
    int b = blockIdx.x;
    int wid = threadIdx.x >> 5, lane = threadIdx.x & 31;
    if (wid < TK) {
        float s = 0.f;
        for (int d = lane; d < DTd; d += 32)
            s += g_bap2[b*DTd + d] * W_fc[d*TK + wid];
        #pragma unroll
        for (int o = 16; o; o >>= 1) s += __shfl_xor_sync(0xffffffffu, s, o);
        if (lane == 0)
            out[(size_t)b*Cd + g_topk[b*TK + wid]] = s + b_fc[wid];
    }
}

// ---------------- launch ----------------------------------------------------
extern "C" void kernel_launch(void* const* d_in, const int* in_sizes, int n_in,
                              void* d_out, int out_size) {
    const float* ftm    = (const float*)d_in[0];
    const float* logits = (const float*)d_in[1];
    const int*   table  = (const int*)  d_in[3];
    const float* w2v    = (const float*)d_in[4];
    const float* W_emb  = (const float*)d_in[5];
    const float* b_emb  = (const float*)d_in[6];
    const float* W_cls  = (const float*)d_in[7];
    const float* b_cls  = (const float*)d_in[8];
    const float* W_v    = (const float*)d_in[9];
    const float* b_v    = (const float*)d_in[10];
    const float* W_bap  = (const float*)d_in[11];
    const float* b_bap  = (const float*)d_in[12];
    const float* W_fc   = (const float*)d_in[13];
    const float* b_fc   = (const float*)d_in[14];
    float* out = (float*)d_out;

    float *p_emb, *p_cls1, *p_cls, *p_v;
    cudaGetSymbolAddress((void**)&p_emb,  g_emb);
    cudaGetSymbolAddress((void**)&p_cls1, g_cls1);
    cudaGetSymbolAddress((void**)&p_cls,  g_cls);
    cudaGetSymbolAddress((void**)&p_v,    g_v);

    cudaFuncSetAttribute(vgemm5_kernel, cudaFuncAttributeMaxDynamicSharedMemorySize, VSMEM5);

    // R14-proven footprint: ONE extra stream, TWO events (reused via re-record).
    cudaStream_t s2;
    cudaEvent_t evF, evJ;
    cudaStreamCreateWithFlags(&s2, cudaStreamNonBlocking);
    cudaEventCreateWithFlags(&evF, cudaEventDisableTiming);
    cudaEventCreateWithFlags(&evJ, cudaEventDisableTiming);

    cudaMemsetAsync(d_out, 0, (size_t)out_size * sizeof(float), 0);
    cudaEventRecord(evF, 0);
    cudaStreamWaitEvent(s2, evF, 0);

    // memset(1) -> topk(2,s2) -> gather(3,s2) -> convW(4) -> vgemm5_h1(5: ncu -s 5)
    topk_kernel<<<Bsz, 256, 0, s2>>>(logits);
    gather_emb_kernel<<<Bsz*TK, 128, 0, s2>>>(table, w2v);
    // cls chain on s2 (finishes well before vgemm half-1 does)
    tgemm_kernel<<<dim3(8, 5, 1), 256, 0, s2>>>(p_emb,  W_emb, b_emb, p_cls1, Bsz*TK, DWd);
    tgemm_kernel<<<dim3(8, 5, 1), 256, 0, s2>>>(p_cls1, W_cls, b_cls, p_cls,  Bsz*TK, DTd);

    convW_kernel<<<dim3(32, 24), 256>>>(W_v);
    // vgemm half-1: batches 0..15
    vgemm5_kernel<<<dim3(8, 6, 16), 256, VSMEM5>>>(ftm, b_v, p_v, 0);
    cudaEventRecord(evF, 0);               // reuse evF: "half-1 done"

    // s2: after cls (program order) + vgemm half-1, run tail for b 0..15
    cudaStreamWaitEvent(s2, evF, 0);
    scores_kernel<<<dim3(11, 16), 256, 0, s2>>>(0);
    bap_kernel   <<<dim3(4,  16), 256, 0, s2>>>(0);
    cudaEventRecord(evJ, s2);              // "side tail done"

    // main: vgemm half-2 (batches 16..63) overlaps s2's tail work
    vgemm5_kernel<<<dim3(8, 6, 48), 256, VSMEM5>>>(ftm, b_v, p_v, 16);

    // main tail for b 16..63, then join
    scores_kernel<<<dim3(11, 48), 256>>>(16);
    bap_kernel   <<<dim3(4,  48), 256>>>(16);
    cudaStreamWaitEvent(0, evJ, 0);
    fcw_kernel   <<<Bsz*4, 256>>>(W_bap, b_bap);
    fc_scatter_kernel<<<Bsz, 320>>>(W_fc, b_fc, out);
}